// round 17
// baseline (speedup 1.0000x reference)
#include <cuda_runtime.h>
#include <cuda_bf16.h>
#include <stdint.h>

// Problem: B=1024 samples, V=2, M=256 latent, C=256 categories.
// out[b] = log( S[x0[b], x1[b]] ),  S[c0,c1] = sum_q W0[q,c0] * (w_k(q) * W1[q,c1])
// q = 65536 km-pairs. Split-K bf16 GEMM via mma.sync (sm_80 ISA, compiles at
// plain compute_103). Warp-specialized: producer warps convert fp32->bf16 into
// a 2-stage smem ring while consumer warps run ldmatrix+mma — phases overlap
// instead of phase-locking (R16's additive fill+mma).

#define B_SZ    1024
#define C_SZ    256
#define W1_OFF  16777216LL        // M*M*C floats = offset of W[1]
#define NCTA    1024              // 4 quadrants x 256 K-chunks
#define KCHUNK  256               // q per CTA (256 | 256 -> w_k CTA-constant)
#define QSUB    32                // q per pipeline subtile
#define NSUB    8                 // KCHUNK / QSUB
#define THREADS 512               // warps 0-7 consumers, 8-15 producers

// bf16 ring: 2 stages x (A 32x128 + B 32x128), 272B row pitch (proven
// conflict-free for both STS and ldmatrix). Epilogue fp32 stage aliases it.
#define APITCH     272
#define STG_BYTES  8704           // 32 * 272
#define STAGE(s)   ((s) * 2 * STG_BYTES)
#define STAGE_B(s) (STAGE(s) + STG_BYTES)
#define SMEM_TOTAL 69632          // >= 128*132*4 epilogue stage
#define STAGE_PITCH 132

__device__ float g_acc[B_SZ];     // indexed by ORIGINAL b
__device__ int   g_cnt;           // CTA completion counter

__device__ __forceinline__ unsigned smem_u32(const void* p) {
    return (unsigned)__cvta_generic_to_shared(p);
}
// pack two fp32 -> bf16x2, f_lo in low half (first cvt source = HIGH half)
__device__ __forceinline__ uint32_t pack_bf16x2(float f_lo, float f_hi) {
    uint32_t r;
    asm("cvt.rn.bf16x2.f32 %0, %1, %2;" : "=r"(r) : "f"(f_hi), "f"(f_lo));
    return r;
}

// ---------------------------------------------------------------------------
// Fused kernel. bid = quadrant(2b) | chunk<<2 (adjacent bids share q-range ->
// L2 dedups the 2x operand read).
//   Producers (warps 8-15, 256 threads): thread (r=pt>>3, seg=pt&7) loads
//   A row q=r cols [seg*16, seg*16+16) as 4 float4 + same for B (scaled wk),
//   converts, STS 2x uint4 per operand. 2-subtile register lookahead.
//   Consumers (warps 0-7): proven R16 fragment code, warp grid 4(m) x 2(n),
//   warp tile 32x64, 2 k-steps per subtile, 64 fp32 accums.
//   Epilogue: accums -> fp32 smem stage; each thread gathers its 2 samples'
//   (x0,x1) hits -> atomicAdd g_acc[b]; last CTA does log + out + state reset.
// ---------------------------------------------------------------------------
__global__ void __launch_bounds__(THREADS, 1)
k_gemm(const int2* __restrict__ x, const float* __restrict__ W,
       const float* __restrict__ w_sum, float* __restrict__ out) {
    extern __shared__ char smem[];
    const int t = threadIdx.x, wid = t >> 5, l = t & 31;
    const int c0b = (blockIdx.x & 1) << 7;
    const int c1b = ((blockIdx.x >> 1) & 1) << 7;
    const int q0g = (int)(blockIdx.x >> 2) * KCHUNK;
    const float wk = __ldg(w_sum + (q0g >> 8));      // k constant per CTA

    const uint32_t smb = smem_u32(smem);
    const bool producer = (wid >= 8);

    // ---------------- producer state ----------------
    const int pt  = t - 256;                         // 0..255 (producers)
    const int pr  = pt >> 3;                         // q-row within subtile
    const int ps  = (pt & 7) * 16;                   // col segment base
    // gmem row base pointers for this thread's (row, seg)
    const float* gA = W + ((long long)q0g + pr) * C_SZ + c0b + ps;
    const float* gB = W + W1_OFF + ((long long)q0g + pr) * C_SZ + c1b + ps;
    float4 bufA[2][4], bufB[2][4];

#define LDG_SUB(buf, sub)                                                     \
    do {                                                                      \
        const float* _a = gA + (long long)(sub) * QSUB * C_SZ;                \
        const float* _b = gB + (long long)(sub) * QSUB * C_SZ;                \
        _Pragma("unroll")                                                     \
        for (int _j = 0; _j < 4; _j++) {                                      \
            bufA[buf][_j] = *(const float4*)(_a + 4 * _j);                    \
            bufB[buf][_j] = *(const float4*)(_b + 4 * _j);                    \
        }                                                                     \
    } while (0)

#define STS_SUB(buf, sub)                                                     \
    do {                                                                      \
        const int _st = (sub) & 1;                                            \
        uint4 _ua, _ub;                                                       \
        _ua.x = pack_bf16x2(bufA[buf][0].x, bufA[buf][0].y);                  \
        _ua.y = pack_bf16x2(bufA[buf][0].z, bufA[buf][0].w);                  \
        _ua.z = pack_bf16x2(bufA[buf][1].x, bufA[buf][1].y);                  \
        _ua.w = pack_bf16x2(bufA[buf][1].z, bufA[buf][1].w);                  \
        *(uint4*)(smem + STAGE(_st) + pr * APITCH + ps * 2) = _ua;            \
        _ua.x = pack_bf16x2(bufA[buf][2].x, bufA[buf][2].y);                  \
        _ua.y = pack_bf16x2(bufA[buf][2].z, bufA[buf][2].w);                  \
        _ua.z = pack_bf16x2(bufA[buf][3].x, bufA[buf][3].y);                  \
        _ua.w = pack_bf16x2(bufA[buf][3].z, bufA[buf][3].w);                  \
        *(uint4*)(smem + STAGE(_st) + pr * APITCH + ps * 2 + 16) = _ua;       \
        _ub.x = pack_bf16x2(bufB[buf][0].x * wk, bufB[buf][0].y * wk);        \
        _ub.y = pack_bf16x2(bufB[buf][0].z * wk, bufB[buf][0].w * wk);        \
        _ub.z = pack_bf16x2(bufB[buf][1].x * wk, bufB[buf][1].y * wk);        \
        _ub.w = pack_bf16x2(bufB[buf][1].z * wk, bufB[buf][1].w * wk);        \
        *(uint4*)(smem + STAGE_B(_st) + pr * APITCH + ps * 2) = _ub;          \
        _ub.x = pack_bf16x2(bufB[buf][2].x * wk, bufB[buf][2].y * wk);        \
        _ub.y = pack_bf16x2(bufB[buf][2].z * wk, bufB[buf][2].w * wk);        \
        _ub.z = pack_bf16x2(bufB[buf][3].x * wk, bufB[buf][3].y * wk);        \
        _ub.w = pack_bf16x2(bufB[buf][3].z * wk, bufB[buf][3].w * wk);        \
        *(uint4*)(smem + STAGE_B(_st) + pr * APITCH + ps * 2 + 16) = _ub;     \
    } while (0)

    // ---------------- consumer state ----------------
    const int wm = wid & 3, wn = wid >> 2;           // consumers: wid 0..7
    float d[2][8][4] = {};

    // ---- prologue: fill stage 0 (and prefetch subtile 1) ----
    if (producer) {
        LDG_SUB(0, 0);
        LDG_SUB(1, 1);
        STS_SUB(0, 0);
    }
    __syncthreads();

    // ---- pipelined mainloop over 8 subtiles ----
    for (int i = 0; i < NSUB; i++) {
        if (producer) {
            if (i + 2 < NSUB) LDG_SUB(i & 1, i + 2);   // buf freed by STS below
            if (i + 1 < NSUB) STS_SUB((i + 1) & 1, i + 1);
        } else {
            const uint32_t smA = smb + STAGE(i & 1);
            const uint32_t smB = smb + STAGE_B(i & 1);
#pragma unroll
            for (int ks = 0; ks < 2; ks++) {
                const int k0 = ks * 16;
                uint32_t a[2][4];
#pragma unroll
                for (int im = 0; im < 2; im++) {
                    const uint32_t krow = (uint32_t)(k0 + (l & 7) + ((l >> 4) << 3));
                    const uint32_t mcol = (uint32_t)(wm * 32 + im * 16 + (l & 8));
                    const uint32_t ad = smA + krow * APITCH + mcol * 2;
                    asm volatile(
                        "ldmatrix.sync.aligned.m8n8.x4.trans.shared.b16 {%0,%1,%2,%3}, [%4];"
                        : "=r"(a[im][0]), "=r"(a[im][1]), "=r"(a[im][2]), "=r"(a[im][3])
                        : "r"(ad));
                }
#pragma unroll
                for (int inb = 0; inb < 4; inb++) {
                    const uint32_t krow = (uint32_t)(k0 + (l & 7) + (l & 8));
                    const uint32_t ncol = (uint32_t)(wn * 64 + inb * 16 + ((l >> 4) << 3));
                    const uint32_t bd = smB + krow * APITCH + ncol * 2;
                    uint32_t b0, b1, b2, b3;
                    asm volatile(
                        "ldmatrix.sync.aligned.m8n8.x4.trans.shared.b16 {%0,%1,%2,%3}, [%4];"
                        : "=r"(b0), "=r"(b1), "=r"(b2), "=r"(b3) : "r"(bd));
#pragma unroll
                    for (int im = 0; im < 2; im++) {
                        asm volatile(
                            "mma.sync.aligned.m16n8k16.row.col.f32.bf16.bf16.f32 "
                            "{%0,%1,%2,%3}, {%4,%5,%6,%7}, {%8,%9}, {%0,%1,%2,%3};"
                            : "+f"(d[im][2*inb][0]), "+f"(d[im][2*inb][1]),
                              "+f"(d[im][2*inb][2]), "+f"(d[im][2*inb][3])
                            : "r"(a[im][0]), "r"(a[im][1]), "r"(a[im][2]), "r"(a[im][3]),
                              "r"(b0), "r"(b1));
                        asm volatile(
                            "mma.sync.aligned.m16n8k16.row.col.f32.bf16.bf16.f32 "
                            "{%0,%1,%2,%3}, {%4,%5,%6,%7}, {%8,%9}, {%0,%1,%2,%3};"
                            : "+f"(d[im][2*inb+1][0]), "+f"(d[im][2*inb+1][1]),
                              "+f"(d[im][2*inb+1][2]), "+f"(d[im][2*inb+1][3])
                            : "r"(a[im][0]), "r"(a[im][1]), "r"(a[im][2]), "r"(a[im][3]),
                              "r"(b2), "r"(b3));
                    }
                }
            }
        }
        __syncthreads();
    }
#undef LDG_SUB
#undef STS_SUB

    // ---- epilogue: stage accums (aliases ring; all reads done), gather ----
    float* stage = (float*)smem;
    if (!producer) {
        const int gr = l >> 2, gc = 2 * (l & 3);
#pragma unroll
        for (int im = 0; im < 2; im++)
#pragma unroll
            for (int jn = 0; jn < 8; jn++) {
                const int m = wm * 32 + im * 16 + gr;
                const int n = wn * 64 + jn * 8 + gc;
                *(float2*)&stage[m * STAGE_PITCH + n] =
                    make_float2(d[im][jn][0], d[im][jn][1]);
                *(float2*)&stage[(m + 8) * STAGE_PITCH + n] =
                    make_float2(d[im][jn][2], d[im][jn][3]);
            }
    }
    __syncthreads();

#pragma unroll
    for (int j = 0; j < 2; j++) {
        const int s = t + 512 * j;
        const int2 v = x[s];                       // (x0, x1)
        const int r = v.x - c0b, c = v.y - c1b;
        if ((unsigned)r < 128u && (unsigned)c < 128u)
            atomicAdd(&g_acc[s], stage[r * STAGE_PITCH + c]);
    }

    // ---- last CTA: log epilogue + state reset (proven R14 pattern) ----
    __shared__ int s_last;
    __threadfence();                     // release: g_acc adds before counter
    if (t == 0) {
        int c = atomicAdd(&g_cnt, 1);
        s_last = (c == NCTA - 1);
    }
    __syncthreads();
    if (s_last) {
        __threadfence();                 // acquire: counter before g_acc reads
#pragma unroll
        for (int j = 0; j < 2; j++) {
            int i = t + 512 * j;
            out[i] = logf(__ldcg(&g_acc[i]));
        }
        __syncthreads();
#pragma unroll
        for (int j = 0; j < 2; j++) g_acc[t + 512 * j] = 0.0f;
        if (t == 0) { __threadfence(); g_cnt = 0; }   // reset for next replay
    }
}

// ---------------------------------------------------------------------------
// Inputs (metadata order): d_in[0]=x int32 [1024,2], d_in[1]=W fp32 [2,256,256,256],
// d_in[2]=w_sum fp32 [256]. Output: fp32 [1024].
// ---------------------------------------------------------------------------
extern "C" void kernel_launch(void* const* d_in, const int* in_sizes, int n_in,
                              void* d_out, int out_size) {
    (void)in_sizes; (void)n_in; (void)out_size;
    const int2*  x     = (const int2*)d_in[0];
    const float* W     = (const float*)d_in[1];
    const float* w_sum = (const float*)d_in[2];
    float*       out   = (float*)d_out;

    static int smem_set = 0;
    if (!smem_set) {
        cudaFuncSetAttribute(k_gemm, cudaFuncAttributeMaxDynamicSharedMemorySize,
                             SMEM_TOTAL);
        smem_set = 1;
    }
    k_gemm<<<NCTA, THREADS, SMEM_TOTAL>>>(x, W, w_sum, out);
}